// round 3
// baseline (speedup 1.0000x reference)
#include <cuda_runtime.h>
#include <cuda_bf16.h>

// LinearSpline activation, division-free:
//   t  = (x*s) * 6.25f                       (6.25f == float(1/0.16), exact)
//   tc = clamp(t, -25.0f, 24.0f)             (== reference clip-then-divide)
//   fl = floor(tc);  fr = t - fl             (fr from unclamped t, per reference)
//   out = fma(fr, c1-c0, c0) * (1/s)
//
// Gather table in SMEM with 12-byte stride cells (c0, c1, pad):
// bank(first word) = (3*idx) % 32, gcd(3,32)=1 -> any 32 consecutive idx hit
// 32 distinct banks; equal idx broadcasts. Gaussian idx spread (~25 +/- 12)
// => conflict-free LDS.32 pairs instead of ~3-4x conflicted LDS.64.

#define NUM_ACT 64
#define SIZE    51
#define TABLE   (NUM_ACT * SIZE)   // 3264

__global__ __launch_bounds__(256, 5)
void linear_spline_kernel(const float4* __restrict__ x,
                          const float*  __restrict__ coef,
                          const float*  __restrict__ scale,
                          float4*       __restrict__ out,
                          int n4)
{
    __shared__ float sc3[TABLE * 3];    // 12B cells: (c[i], c[i+1], pad) -> 39 KB
    __shared__ float2 ssc[NUM_ACT];     // (s, 1/s)

    for (int i = threadIdx.x; i < TABLE; i += 256) {
        float a = coef[i];
        float b = (i + 1 < TABLE) ? coef[i + 1] : 0.0f;  // edge cell never dereferenced
        sc3[3 * i]     = a;
        sc3[3 * i + 1] = b;
    }
    if (threadIdx.x < NUM_ACT) {
        float s = scale[threadIdx.x];
        ssc[threadIdx.x] = make_float2(s, 1.0f / s);     // exact for s==1
    }
    __syncthreads();

    const float rg = 6.25f;
    const int stride = gridDim.x * blockDim.x;
    int i = blockIdx.x * blockDim.x + threadIdx.x;

    // One element: ~12 SASS ops + 2 conflict-free LDS.32, zero divisions.
    #define ELEM(v, ov, zk3_, s_, rs_) {                 \
        float xs = (v) * (s_);                           \
        float t  = xs * rg;                              \
        float tc = fminf(fmaxf(t, -25.0f), 24.0f);       \
        float fl = floorf(tc);                           \
        float fr = t - fl;                               \
        int p = (zk3_) + 3 * (int)fl;                    \
        float c0 = sc3[p];                               \
        float c1 = sc3[p + 1];                           \
        (ov) = fmaf(fr, c1 - c0, c0) * (rs_); }

    // ILP=2: two independent float4 tiles in flight per trip.
    for (; i + stride < n4; i += 2 * stride) {
        const int j = i + stride;
        float4 xa = __ldcs(&x[i]);          // streaming: no reuse
        float4 xb = __ldcs(&x[j]);

        const int ca = (i >> 12) & (NUM_ACT - 1);   // 4096 float4 per channel
        const int cb = (j >> 12) & (NUM_ACT - 1);
        const float2 sva = ssc[ca];
        const float2 svb = ssc[cb];
        const int zka3 = ca * (SIZE * 3) + (SIZE / 2) * 3;
        const int zkb3 = cb * (SIZE * 3) + (SIZE / 2) * 3;

        float4 oa, ob;
        ELEM(xa.x, oa.x, zka3, sva.x, sva.y)
        ELEM(xa.y, oa.y, zka3, sva.x, sva.y)
        ELEM(xa.z, oa.z, zka3, sva.x, sva.y)
        ELEM(xa.w, oa.w, zka3, sva.x, sva.y)
        ELEM(xb.x, ob.x, zkb3, svb.x, svb.y)
        ELEM(xb.y, ob.y, zkb3, svb.x, svb.y)
        ELEM(xb.z, ob.z, zkb3, svb.x, svb.y)
        ELEM(xb.w, ob.w, zkb3, svb.x, svb.y)

        __stcs(&out[i], oa);
        __stcs(&out[j], ob);
    }
    if (i < n4) {
        float4 xv = __ldcs(&x[i]);
        const int c = (i >> 12) & (NUM_ACT - 1);
        const float2 sv = ssc[c];
        const int zk3 = c * (SIZE * 3) + (SIZE / 2) * 3;
        float4 o;
        ELEM(xv.x, o.x, zk3, sv.x, sv.y)
        ELEM(xv.y, o.y, zk3, sv.x, sv.y)
        ELEM(xv.z, o.z, zk3, sv.x, sv.y)
        ELEM(xv.w, o.w, zk3, sv.x, sv.y)
        __stcs(&out[i], o);
    }
    #undef ELEM
}

extern "C" void kernel_launch(void* const* d_in, const int* in_sizes, int n_in,
                              void* d_out, int out_size)
{
    const float* x     = (const float*)d_in[0];
    const float* coef  = (const float*)d_in[1];
    const float* scale = (const float*)d_in[2];
    float* out         = (float*)d_out;

    const int n  = in_sizes[0];   // 33,554,432
    const int n4 = n / 4;         // 8,388,608

    const int threads = 256;
    const int blocks  = 148 * 5;  // 5 CTAs/SM (39 KB smem each), single wave

    linear_spline_kernel<<<blocks, threads>>>(
        (const float4*)x, coef, scale, (float4*)out, n4);
}

// round 4
// speedup vs baseline: 1.0482x; 1.0482x over previous
#include <cuda_runtime.h>
#include <cuda_bf16.h>

// LinearSpline activation, division-free:
//   t  = (x*s) * 6.25f                     (6.25f == float(1/0.16), exact)
//   tc = clamp(t, -25.0f, 24.0f)           (== reference clip-then-divide)
//   fl = floor(tc);  fr = t - fl           (fr from unclamped t, per reference)
//   out = fma(fr, c1-c0, c0) * (1/s)
//
// Latency-bound streaming kernel: throughput ~ warps x in-flight LDG.128.
// R4: ILP=4 (4 independent LDG.128 issued up front per trip) at 4 CTAs/SM
// (32 warps, 64-reg budget) -> 128 in-flight units vs 96 (R2) / 80 (R3).
// Gather table: 12-byte cells (c0, c1, pad); bank = (3*idx)%32, gcd(3,32)=1
// -> conflict-free for the Gaussian-concentrated idx window.

#define NUM_ACT 64
#define SIZE    51
#define TABLE   (NUM_ACT * SIZE)   // 3264

__global__ __launch_bounds__(256, 4)
void linear_spline_kernel(const float4* __restrict__ x,
                          const float*  __restrict__ coef,
                          const float*  __restrict__ scale,
                          float4*       __restrict__ out,
                          int n4)
{
    __shared__ float  sc3[TABLE * 3];   // (c[i], c[i+1], pad) cells, 39 KB
    __shared__ float2 ssc[NUM_ACT];     // (s, 1/s)

    for (int i = threadIdx.x; i < TABLE; i += 256) {
        float a = coef[i];
        float b = (i + 1 < TABLE) ? coef[i + 1] : 0.0f;  // edge cell never dereferenced
        sc3[3 * i]     = a;
        sc3[3 * i + 1] = b;
    }
    if (threadIdx.x < NUM_ACT) {
        float s = scale[threadIdx.x];
        ssc[threadIdx.x] = make_float2(s, 1.0f / s);     // exact for s==1
    }
    __syncthreads();

    const float rg = 6.25f;
    const int stride = gridDim.x * blockDim.x;
    int i = blockIdx.x * blockDim.x + threadIdx.x;

    #define ELEM(v, ov, zk3_, s_, rs_) {                 \
        float xs = (v) * (s_);                           \
        float t  = xs * rg;                              \
        float tc = fminf(fmaxf(t, -25.0f), 24.0f);       \
        float fl = floorf(tc);                           \
        float fr = t - fl;                               \
        int p = (zk3_) + 3 * (int)fl;                    \
        float c0 = sc3[p];                               \
        float c1 = sc3[p + 1];                           \
        (ov) = fmaf(fr, c1 - c0, c0) * (rs_); }

    // ILP=4: four independent LDG.128 in flight before any dependent compute.
    for (; i + 3 * stride < n4; i += 4 * stride) {
        float4 xv[4];
        #pragma unroll
        for (int u = 0; u < 4; u++) xv[u] = x[i + u * stride];

        #pragma unroll
        for (int u = 0; u < 4; u++) {
            const int j = i + u * stride;
            const int c = (j >> 12) & (NUM_ACT - 1);    // 4096 float4 per channel
            const float2 sv = ssc[c];
            const int zk3 = c * (SIZE * 3) + (SIZE / 2) * 3;
            float4 o;
            ELEM(xv[u].x, o.x, zk3, sv.x, sv.y)
            ELEM(xv[u].y, o.y, zk3, sv.x, sv.y)
            ELEM(xv[u].z, o.z, zk3, sv.x, sv.y)
            ELEM(xv[u].w, o.w, zk3, sv.x, sv.y)
            out[j] = o;
        }
    }
    // tail: up to 3 more trips per thread
    for (; i < n4; i += stride) {
        float4 xv = x[i];
        const int c = (i >> 12) & (NUM_ACT - 1);
        const float2 sv = ssc[c];
        const int zk3 = c * (SIZE * 3) + (SIZE / 2) * 3;
        float4 o;
        ELEM(xv.x, o.x, zk3, sv.x, sv.y)
        ELEM(xv.y, o.y, zk3, sv.x, sv.y)
        ELEM(xv.z, o.z, zk3, sv.x, sv.y)
        ELEM(xv.w, o.w, zk3, sv.x, sv.y)
        out[i] = o;
    }
    #undef ELEM
}

extern "C" void kernel_launch(void* const* d_in, const int* in_sizes, int n_in,
                              void* d_out, int out_size)
{
    const float* x     = (const float*)d_in[0];
    const float* coef  = (const float*)d_in[1];
    const float* scale = (const float*)d_in[2];
    float* out         = (float*)d_out;

    const int n  = in_sizes[0];   // 33,554,432
    const int n4 = n / 4;         // 8,388,608

    const int threads = 256;
    const int blocks  = 148 * 4;  // 4 CTAs/SM, ILP=4 -> 128 in-flight units/SM

    linear_spline_kernel<<<blocks, threads>>>(
        (const float4*)x, coef, scale, (float4*)out, n4);
}